// round 5
// baseline (speedup 1.0000x reference)
#include <cuda_runtime.h>

#define SEQ   1024
#define BATCH 512
#define INF   128
#define HID   256

typedef unsigned long long u64;

__device__ __forceinline__ u64 pack2(float lo, float hi) {
    u64 r; asm("mov.b64 %0, {%1, %2};" : "=l"(r) : "f"(lo), "f"(hi)); return r;
}
__device__ __forceinline__ void unpack2(u64 v, float& lo, float& hi) {
    asm("mov.b64 {%0, %1}, %2;" : "=f"(lo), "=f"(hi) : "l"(v));
}
__device__ __forceinline__ u64 ffma2(u64 a, u64 b, u64 c) {
    u64 d; asm("fma.rn.f32x2 %0, %1, %2, %3;" : "=l"(d) : "l"(a), "l"(b), "l"(c));
    return d;
}

// ---------------------------------------------------------------------------
// Kernel 1: x_proj = input @ W_in + (b_in + b_hh) -> d_out.
// Thread (j2, half): columns c0=j2, c1=j2+128; k-range [half*64, half*64+64).
// All weights in registers (64 u64). Partner lanes (xor 1) hold the other
// k-half; partial sums combined via shfl.bfly. 8 x-rows staged in smem,
// double buffered; each 16B broadcast LDS feeds 4 FFMA2.
// ---------------------------------------------------------------------------
__global__ void __launch_bounds__(256, 1) xproj_kernel(
    const float* __restrict__ input, const float* __restrict__ Win,
    const float* __restrict__ b_in,  const float* __restrict__ b_hh,
    float* __restrict__ out)
{
    __shared__ float xs[2][8 * INF];
    const int t    = threadIdx.x;
    const int j2   = t >> 1;
    const int half = t & 1;
    const int koff = half * 64;
    const int c0   = j2, c1 = j2 + 128;

    u64 WA[32], WB[32];                 // k-pairs for c0 / c1, half k-range
#pragma unroll
    for (int k2 = 0; k2 < 32; ++k2) {
        WA[k2] = pack2(Win[(koff + 2 * k2) * HID + c0],
                       Win[(koff + 2 * k2 + 1) * HID + c0]);
        WB[k2] = pack2(Win[(koff + 2 * k2) * HID + c1],
                       Win[(koff + 2 * k2 + 1) * HID + c1]);
    }
    const float biasA = b_in[c0] + b_hh[c0];
    const float biasB = b_in[c1] + b_hh[c1];

    const int nchunks = (SEQ * BATCH) / 8;
    int c = blockIdx.x;
    if (c >= nchunks) return;

    ((float4*)xs[0])[t] = ((const float4*)(input + (long)c * 8 * INF))[t];
    __syncthreads();

    int p = 0;
    while (c < nchunks) {
        const int  cn  = c + gridDim.x;
        const bool has = (cn < nchunks);
        float4 nxt;
        if (has) nxt = ((const float4*)(input + (long)cn * 8 * INF))[t];

        u64 accA[8], accB[8];
#pragma unroll
        for (int r = 0; r < 8; ++r) { accA[r] = 0ull; accB[r] = 0ull; }

        const float* xb = xs[p];
#pragma unroll
        for (int k4 = 0; k4 < 16; ++k4) {            // 4 k-values per iter
#pragma unroll
            for (int r = 0; r < 8; ++r) {
                ulonglong2 h2 = *(const ulonglong2*)(xb + r * INF + koff + 4 * k4);
                accA[r] = ffma2(WA[2 * k4 + 0], h2.x, accA[r]);
                accA[r] = ffma2(WA[2 * k4 + 1], h2.y, accA[r]);
                accB[r] = ffma2(WB[2 * k4 + 0], h2.x, accB[r]);
                accB[r] = ffma2(WB[2 * k4 + 1], h2.y, accB[r]);
            }
        }

        // combine halves: partner lane (xor 1) has the other k-half
        float sA[8], sB[8];
#pragma unroll
        for (int r = 0; r < 8; ++r) {
            float lo, hi;
            unpack2(accA[r], lo, hi); sA[r] = lo + hi;
            sA[r] += __shfl_xor_sync(0xffffffffu, sA[r], 1);
            unpack2(accB[r], lo, hi); sB[r] = lo + hi;
            sB[r] += __shfl_xor_sync(0xffffffffu, sB[r], 1);
        }

        // half0 writes rows 0-3, half1 rows 4-7 (both columns)
        const long base = (long)c * 8 + half * 4;
#pragma unroll
        for (int r = 0; r < 4; ++r) {
            out[(base + r) * HID + c0] = sA[half * 4 + r] + biasA;
            out[(base + r) * HID + c1] = sB[half * 4 + r] + biasB;
        }

        if (has) ((float4*)xs[p ^ 1])[t] = nxt;
        __syncthreads();
        p ^= 1;
        c = cn;
    }
}

// ---------------------------------------------------------------------------
// Kernel 2: recurrent scan, 128 CTAs x 4 batch rows, 256 threads.
// Thread (j2, half): columns c0=j2, c1=j2+128; k-range [half*128, +128).
// ALL W_hh weights in registers (64 u64) -> zero weight LDS.
// h in smem [b][k], double buffered, 1 barrier/step. Each 16B broadcast
// h-load feeds 4 FFMA2. Partner-lane shfl.bfly combines the k-halves.
// ---------------------------------------------------------------------------
__global__ void __launch_bounds__(256, 1) rnn_scan_kernel(
    float* __restrict__ xo,            // d_out: xp in, h out (same locations)
    const float* __restrict__ hidden0,
    const float* __restrict__ Whh,
    float* __restrict__ hlast)
{
    __shared__ float hbuf[2][4 * HID];

    const int t    = threadIdx.x;
    const int j2   = t >> 1;
    const int half = t & 1;
    const int koff = half * 128;
    const int c0   = j2, c1 = j2 + 128;
    const int b0   = blockIdx.x * 4;
    const int myb  = half * 2;          // this thread finalizes batches myb, myb+1

    u64 WA[64], WB[64];                 // k-pairs, half k-range, 2 columns
#pragma unroll
    for (int k2 = 0; k2 < 64; ++k2) {
        WA[k2] = pack2(Whh[(koff + 2 * k2) * HID + c0],
                       Whh[(koff + 2 * k2 + 1) * HID + c0]);
        WB[k2] = pack2(Whh[(koff + 2 * k2) * HID + c1],
                       Whh[(koff + 2 * k2 + 1) * HID + c1]);
    }

    for (int idx = t; idx < 4 * HID; idx += 256) {
        int b = idx >> 8, k = idx & 255;
        hbuf[0][idx] = hidden0[(b0 + b) * HID + k];
    }
    __syncthreads();

    // xp for the 4 outputs this thread owns: (b=myb..myb+1) x (c0,c1)
    float xp_cur[4], xp_nxt[4];
#pragma unroll
    for (int i = 0; i < 2; ++i) {
        xp_cur[2 * i + 0] = xo[(long)(b0 + myb + i) * HID + c0];
        xp_cur[2 * i + 1] = xo[(long)(b0 + myb + i) * HID + c1];
    }

    float hl[4];
    int p = 0;

    for (int s = 0; s < SEQ; ++s) {
        if (s + 1 < SEQ) {
#pragma unroll
            for (int i = 0; i < 2; ++i) {
                const long rb = ((long)(s + 1) * BATCH + b0 + myb + i) * HID;
                xp_nxt[2 * i + 0] = xo[rb + c0];
                xp_nxt[2 * i + 1] = xo[rb + c1];
            }
        }

        const float* hc = hbuf[p];
        float*       hn = hbuf[p ^ 1];

        u64 accA[4], accB[4];
#pragma unroll
        for (int b = 0; b < 4; ++b) { accA[b] = 0ull; accB[b] = 0ull; }

#pragma unroll
        for (int k4 = 0; k4 < 32; ++k4) {            // 4 k-values per iter
#pragma unroll
            for (int b = 0; b < 4; ++b) {
                ulonglong2 h2 = *(const ulonglong2*)(hc + b * HID + koff + 4 * k4);
                accA[b] = ffma2(WA[2 * k4 + 0], h2.x, accA[b]);
                accA[b] = ffma2(WA[2 * k4 + 1], h2.y, accA[b]);
                accB[b] = ffma2(WB[2 * k4 + 0], h2.x, accB[b]);
                accB[b] = ffma2(WB[2 * k4 + 1], h2.y, accB[b]);
            }
        }

        // combine the two k-halves across partner lanes
        float sA[4], sB[4];
#pragma unroll
        for (int b = 0; b < 4; ++b) {
            float lo, hi;
            unpack2(accA[b], lo, hi); sA[b] = lo + hi;
            sA[b] += __shfl_xor_sync(0xffffffffu, sA[b], 1);
            unpack2(accB[b], lo, hi); sB[b] = lo + hi;
            sB[b] += __shfl_xor_sync(0xffffffffu, sB[b], 1);
        }

        // epilogue for this thread's 4 outputs
#pragma unroll
        for (int i = 0; i < 2; ++i) {
            const int  b  = myb + i;
            const long ob = ((long)s * BATCH + b0 + b) * HID;

            float pre0 = sA[b] + xp_cur[2 * i + 0];
            float h0   = hc[b * HID + c0];
            float v0   = 0.8f * h0 + 0.2f * fmaxf(pre0, 0.f);
            xo[ob + c0]      = v0;
            hn[b * HID + c0] = v0;

            float pre1 = sB[b] + xp_cur[2 * i + 1];
            float h1   = hc[b * HID + c1];
            float v1   = 0.8f * h1 + 0.2f * fmaxf(pre1, 0.f);
            xo[ob + c1]      = v1;
            hn[b * HID + c1] = v1;

            if (s == SEQ - 1) { hl[2 * i] = v0; hl[2 * i + 1] = v1; }
        }

        __syncthreads();
        p ^= 1;
#pragma unroll
        for (int i = 0; i < 4; ++i) xp_cur[i] = xp_nxt[i];
    }

#pragma unroll
    for (int i = 0; i < 2; ++i) {
        hlast[(long)(b0 + myb + i) * HID + c0] = hl[2 * i];
        hlast[(long)(b0 + myb + i) * HID + c1] = hl[2 * i + 1];
    }
}

// ---------------------------------------------------------------------------
extern "C" void kernel_launch(void* const* d_in, const int* in_sizes, int n_in,
                              void* d_out, int out_size) {
    const float* input  = (const float*)d_in[0];
    const float* hidden = (const float*)d_in[1];
    const float* Win    = (const float*)d_in[2];
    const float* b_in   = (const float*)d_in[3];
    const float* Whh    = (const float*)d_in[4];
    const float* b_hh   = (const float*)d_in[5];

    float* out   = (float*)d_out;                          // [SEQ,BATCH,HID]
    float* hlast = out + (long)SEQ * BATCH * HID;          // [BATCH,HID] tail

    xproj_kernel<<<148, 256>>>(input, Win, b_in, b_hh, out);
    rnn_scan_kernel<<<BATCH / 4, 256>>>(out, hidden, Whh, hlast);
}

// round 8
// speedup vs baseline: 1.3055x; 1.3055x over previous
#include <cuda_runtime.h>

#define SEQ   1024
#define BATCH 512
#define INF   128
#define HID   256

typedef unsigned long long u64;

__device__ __forceinline__ u64 pack2(float lo, float hi) {
    u64 r; asm("mov.b64 %0, {%1, %2};" : "=l"(r) : "f"(lo), "f"(hi)); return r;
}
__device__ __forceinline__ void unpack2(u64 v, float& lo, float& hi) {
    asm("mov.b64 {%0, %1}, %2;" : "=f"(lo), "=f"(hi) : "l"(v));
}
__device__ __forceinline__ u64 ffma2(u64 a, u64 b, u64 c) {
    u64 d; asm("fma.rn.f32x2 %0, %1, %2, %3;" : "=l"(d) : "l"(a), "l"(b), "l"(c));
    return d;
}
__device__ __forceinline__ float sum2(u64 v) {
    float lo, hi; unpack2(v, lo, hi); return lo + hi;
}
__device__ __forceinline__ float red4(float v) {   // sum over quad (lanes ^1, ^2)
    v += __shfl_xor_sync(0xffffffffu, v, 1);
    v += __shfl_xor_sync(0xffffffffu, v, 2);
    return v;
}

// ---------------------------------------------------------------------------
// Kernel 1: x_proj = input @ W_in + (b_in + b_hh) -> d_out.
// 512 threads: thread (j, khalf) -> column j, k in [64*khalf, 64*khalf+64).
// Weights all-register (32 u64). x rows staged in smem with +4 pad per 64-k
// chunk (bank-conflict-free for the 2 khalf offsets). Partner lanes (^1)
// hold the other k-half; combined with one shfl.bfly per row.
// ---------------------------------------------------------------------------
#define XROW 136                       // 2 chunks of (64 data + 4 pad) floats

__global__ void __launch_bounds__(512, 1) xproj_kernel(
    const float* __restrict__ input, const float* __restrict__ Win,
    const float* __restrict__ b_in,  const float* __restrict__ b_hh,
    float* __restrict__ out)
{
    __shared__ float xs[2][8 * XROW];
    const int t     = threadIdx.x;
    const int j     = t >> 1;
    const int khalf = t & 1;
    const int koff  = khalf * 64;

    u64 W2[32];                        // k-pairs of W_in[:, j], own k-half
#pragma unroll
    for (int k2 = 0; k2 < 32; ++k2)
        W2[k2] = pack2(Win[(koff + 2 * k2) * HID + j],
                       Win[(koff + 2 * k2 + 1) * HID + j]);
    const float bias = b_in[j] + b_hh[j];

    // staging map: thread t loads one float2 of the 8x128 chunk
    const int srow = t >> 6;           // 0..7
    const int sk   = (t & 63) * 2;     // 0..126
    const int sdst = srow * XROW + (sk >> 6) * 68 + (sk & 63);

    const int nchunks = (SEQ * BATCH) / 8;
    int c = blockIdx.x;
    if (c >= nchunks) return;

    *(float2*)&xs[0][sdst] = *(const float2*)(input + (long)c * 1024 + srow * 128 + sk);
    __syncthreads();

    int p = 0;
    while (c < nchunks) {
        const int  cn  = c + gridDim.x;
        const bool has = (cn < nchunks);
        float2 nxt;
        if (has) nxt = *(const float2*)(input + (long)cn * 1024 + srow * 128 + sk);

        u64 acc[8];
#pragma unroll
        for (int r = 0; r < 8; ++r) acc[r] = 0ull;

        const float* xb = xs[p];
#pragma unroll
        for (int k4 = 0; k4 < 16; ++k4) {
#pragma unroll
            for (int r = 0; r < 8; ++r) {
                ulonglong2 h2 = *(const ulonglong2*)(xb + r * XROW + khalf * 68 + 4 * k4);
                acc[r] = ffma2(W2[2 * k4 + 0], h2.x, acc[r]);
                acc[r] = ffma2(W2[2 * k4 + 1], h2.y, acc[r]);
            }
        }

        float s[8];
#pragma unroll
        for (int r = 0; r < 8; ++r) {
            s[r] = sum2(acc[r]);
            s[r] += __shfl_xor_sync(0xffffffffu, s[r], 1);
        }

        // khalf0 writes rows 0-3, khalf1 rows 4-7
        const long base = (long)c * 8 + khalf * 4;
#pragma unroll
        for (int r = 0; r < 4; ++r)
            out[(base + r) * HID + j] = s[khalf * 4 + r] + bias;

        if (has) *(float2*)&xs[p ^ 1][sdst] = nxt;
        __syncthreads();
        p ^= 1;
        c = cn;
    }
}

// ---------------------------------------------------------------------------
// Kernel 2: recurrent scan. 128 CTAs x 4 batch rows, 512 threads.
// Thread (j2, q): columns c0=j2, c1=j2+128; k in [64q, 64q+64).
// Weights: reg column (32 u64) + smem column (per-thread row, stride 68).
// h in smem [b][272] (64+4 pad per chunk -> quarter offsets hit distinct
// banks; each h LDS.128 = 1 wavefront carrying 64B). Double buffered,
// 1 barrier/step. Quad shfl.bfly combines k-quarters; lane q finalizes
// batch q for both columns.
// ---------------------------------------------------------------------------
#define WROW 68                        // 64 weights + 4 pad
#define HROW 272                       // 4 chunks of 68 per batch row

__device__ __forceinline__ int hpos(int c) {       // column -> padded offset
    return (c >> 6) * 68 + (c & 63);
}

__global__ void __launch_bounds__(512, 1) rnn_scan_kernel(
    float* __restrict__ xo,            // d_out: xp in, h out (same locations)
    const float* __restrict__ hidden0,
    const float* __restrict__ Whh,
    float* __restrict__ hlast)
{
    extern __shared__ float sm[];
    float* Wt   = sm;                  // [512][WROW]
    float* hbuf = sm + 512 * WROW;     // 2 x [4][HROW]

    const int t    = threadIdx.x;
    const int j2   = t >> 2;           // 0..127
    const int q    = t & 3;            // k-quarter
    const int koff = q * 64;
    const int c0   = j2, c1 = j2 + 128;
    const int cr   = (q & 1) ? c1 : c0;            // register column
    const int cs   = (q & 1) ? c0 : c1;            // smem column
    const int b0   = blockIdx.x * 4;
    const int myb  = q;                             // finalized batch

    u64 WR[32];
#pragma unroll
    for (int k2 = 0; k2 < 32; ++k2)
        WR[k2] = pack2(Whh[(koff + 2 * k2) * HID + cr],
                       Whh[(koff + 2 * k2 + 1) * HID + cr]);
    for (int i = 0; i < 64; ++i)
        Wt[t * WROW + i] = Whh[(koff + i) * HID + cs];

    for (int idx = t; idx < 4 * HID; idx += 512) {
        int b = idx >> 8, k = idx & 255;
        hbuf[b * HROW + hpos(k)] = hidden0[(b0 + b) * HID + k];
    }
    __syncthreads();

    const int p0 = hpos(c0), p1 = hpos(c1);
    float hold0 = hidden0[(b0 + myb) * HID + c0];
    float hold1 = hidden0[(b0 + myb) * HID + c1];

    float xp0 = xo[(long)(b0 + myb) * HID + c0];
    float xp1 = xo[(long)(b0 + myb) * HID + c1];

    int p = 0;
    for (int s = 0; s < SEQ; ++s) {
        float xn0, xn1;
        if (s + 1 < SEQ) {
            const long rb = ((long)(s + 1) * BATCH + b0 + myb) * HID;
            xn0 = xo[rb + c0];
            xn1 = xo[rb + c1];
        }

        const float* hc = hbuf + p * 4 * HROW;
        float*       hn = hbuf + (p ^ 1) * 4 * HROW;

        u64 aR[4], aS[4];
#pragma unroll
        for (int b = 0; b < 4; ++b) { aR[b] = 0ull; aS[b] = 0ull; }

        const float* wrow = Wt + t * WROW;
#pragma unroll
        for (int k4 = 0; k4 < 16; ++k4) {
            ulonglong2 w2 = *(const ulonglong2*)(wrow + 4 * k4);   // conflict-free
#pragma unroll
            for (int b = 0; b < 4; ++b) {
                ulonglong2 h2 = *(const ulonglong2*)(hc + b * HROW + q * 68 + 4 * k4);
                aR[b] = ffma2(WR[2 * k4 + 0], h2.x, aR[b]);
                aR[b] = ffma2(WR[2 * k4 + 1], h2.y, aR[b]);
                aS[b] = ffma2(w2.x, h2.x, aS[b]);
                aS[b] = ffma2(w2.y, h2.y, aS[b]);
            }
        }

        // map (reg,smem) partials to (c0,c1), reduce across the quad
        float s00, s01, s02, s03, s10, s11, s12, s13;
        {
            const bool sw = (q & 1);
            s00 = red4(sw ? sum2(aS[0]) : sum2(aR[0]));
            s01 = red4(sw ? sum2(aS[1]) : sum2(aR[1]));
            s02 = red4(sw ? sum2(aS[2]) : sum2(aR[2]));
            s03 = red4(sw ? sum2(aS[3]) : sum2(aR[3]));
            s10 = red4(sw ? sum2(aR[0]) : sum2(aS[0]));
            s11 = red4(sw ? sum2(aR[1]) : sum2(aS[1]));
            s12 = red4(sw ? sum2(aR[2]) : sum2(aS[2]));
            s13 = red4(sw ? sum2(aR[3]) : sum2(aS[3]));
        }
        float pc0 = (q == 0) ? s00 : (q == 1) ? s01 : (q == 2) ? s02 : s03;
        float pc1 = (q == 0) ? s10 : (q == 1) ? s11 : (q == 2) ? s12 : s13;

        float v0 = 0.8f * hold0 + 0.2f * fmaxf(pc0 + xp0, 0.f);
        float v1 = 0.8f * hold1 + 0.2f * fmaxf(pc1 + xp1, 0.f);

        const long ob = ((long)s * BATCH + b0 + myb) * HID;
        xo[ob + c0] = v0;
        xo[ob + c1] = v1;
        hn[myb * HROW + p0] = v0;
        hn[myb * HROW + p1] = v1;

        hold0 = v0; hold1 = v1;
        xp0 = xn0;  xp1 = xn1;

        __syncthreads();
        p ^= 1;
    }

    hlast[(long)(b0 + myb) * HID + c0] = hold0;
    hlast[(long)(b0 + myb) * HID + c1] = hold1;
}

// ---------------------------------------------------------------------------
extern "C" void kernel_launch(void* const* d_in, const int* in_sizes, int n_in,
                              void* d_out, int out_size) {
    const float* input  = (const float*)d_in[0];
    const float* hidden = (const float*)d_in[1];
    const float* Win    = (const float*)d_in[2];
    const float* b_in   = (const float*)d_in[3];
    const float* Whh    = (const float*)d_in[4];
    const float* b_hh   = (const float*)d_in[5];

    float* out   = (float*)d_out;                          // [SEQ,BATCH,HID]
    float* hlast = out + (long)SEQ * BATCH * HID;          // [BATCH,HID] tail

    xproj_kernel<<<148, 512>>>(input, Win, b_in, b_hh, out);

    const int smem = (512 * WROW + 2 * 4 * HROW) * (int)sizeof(float); // 147968 B
    cudaFuncSetAttribute(rnn_scan_kernel,
                         cudaFuncAttributeMaxDynamicSharedMemorySize, smem);
    rnn_scan_kernel<<<BATCH / 4, 512, smem>>>(out, hidden, Whh, hlast);
}